// round 4
// baseline (speedup 1.0000x reference)
#include <cuda_runtime.h>
#include <cuda_fp16.h>
#include <cstdint>

#define NUM_USERS 100000
#define NUM_ITEMS 200000
#define NN (NUM_USERS + NUM_ITEMS)   // 300000
#define EE 2000000
#define DD 64
#define TOT (NN * DD)                // 19,200,000
#define TOT4 (TOT / 4)
#define TOT8 (TOT / 8)
#define U8  (NUM_USERS * DD / 8)
#define UD4 (NUM_USERS * DD / 4)

// fp16 scratch: h0 = ego in fp16; bufA ends holding h1+h3; bufB holds h2.
__device__ __half g_h0[TOT];
__device__ __half g_bufA[TOT];
__device__ __half g_bufB[TOT];

__device__ __forceinline__ uint32_t h2u(__half2 h) {
    return *reinterpret_cast<uint32_t*>(&h);
}
__device__ __forceinline__ __half2 u2h(uint32_t u) {
    return *reinterpret_cast<__half2*>(&u);
}

// ---------------------------------------------------------------------------
// conv: g_h0 = fp16(concat(ue, ie)); bufA = bufB = 0.
// ---------------------------------------------------------------------------
__global__ void __launch_bounds__(256) conv_kernel(const float4* __restrict__ ue,
                                                   const float4* __restrict__ ie) {
    int i = blockIdx.x * blockDim.x + threadIdx.x;
    if (i >= TOT8) return;
    float4 f0, f1;
    if (i < U8) {
        f0 = __ldg(&ue[2 * i]);
        f1 = __ldg(&ue[2 * i + 1]);
    } else {
        f0 = __ldg(&ie[2 * (i - U8)]);
        f1 = __ldg(&ie[2 * (i - U8) + 1]);
    }
    uint4 h;
    h.x = h2u(__float22half2_rn(make_float2(f0.x, f0.y)));
    h.y = h2u(__float22half2_rn(make_float2(f0.z, f0.w)));
    h.z = h2u(__float22half2_rn(make_float2(f1.x, f1.y)));
    h.w = h2u(__float22half2_rn(make_float2(f1.z, f1.w)));
    reinterpret_cast<uint4*>(g_h0)[i] = h;
    const uint4 z = make_uint4(0u, 0u, 0u, 0u);
    reinterpret_cast<uint4*>(g_bufA)[i] = z;
    reinterpret_cast<uint4*>(g_bufB)[i] = z;
}

// ---------------------------------------------------------------------------
// SpMM (fp16): 4 threads/edge; each thread handles 32B = 2 uint4 gathers
// (MLP=2) + 2 vectorized f16x2 reductions. Edge metadata streamed (__ldcs).
// ---------------------------------------------------------------------------
__global__ void __launch_bounds__(256) spmm_kernel(
    const int* __restrict__ rows, const int* __restrict__ cols,
    const float* __restrict__ vals,
    const __half* __restrict__ src, __half* __restrict__ dst) {
    int t = blockIdx.x * blockDim.x + threadIdx.x;
    int e = t >> 2;
    if (e >= EE) return;
    int ch = (t & 3) << 4;               // half offset 0,16,32,48 (32B chunks)
    int r = __ldcs(&rows[e]);
    int c = __ldcs(&cols[e]);
    float v = __ldcs(&vals[e]);
    const __half* srow = src + (size_t)c * DD + ch;
    uint4 x0 = __ldg(reinterpret_cast<const uint4*>(srow));
    uint4 x1 = __ldg(reinterpret_cast<const uint4*>(srow + 8));
    __half2 vv = __float2half2_rn(v);
    uint32_t a0 = h2u(__hmul2(u2h(x0.x), vv));
    uint32_t a1 = h2u(__hmul2(u2h(x0.y), vv));
    uint32_t a2 = h2u(__hmul2(u2h(x0.z), vv));
    uint32_t a3 = h2u(__hmul2(u2h(x0.w), vv));
    uint32_t b0 = h2u(__hmul2(u2h(x1.x), vv));
    uint32_t b1 = h2u(__hmul2(u2h(x1.y), vv));
    uint32_t b2 = h2u(__hmul2(u2h(x1.z), vv));
    uint32_t b3 = h2u(__hmul2(u2h(x1.w), vv));
    __half* p = dst + (size_t)r * DD + ch;
    asm volatile("red.global.add.noftz.v4.f16x2 [%0], {%1, %2, %3, %4};"
                 :: "l"(p), "r"(a0), "r"(a1), "r"(a2), "r"(a3)
                 : "memory");
    asm volatile("red.global.add.noftz.v4.f16x2 [%0], {%1, %2, %3, %4};"
                 :: "l"(p + 8), "r"(b0), "r"(b1), "r"(b2), "r"(b3)
                 : "memory");
}

// ---------------------------------------------------------------------------
// final: out = (ego_fp32 + (h1+h3) + h2) * 0.25
// ---------------------------------------------------------------------------
__global__ void __launch_bounds__(256) final_kernel(const float4* __restrict__ ue,
                                                    const float4* __restrict__ ie,
                                                    float4* __restrict__ out) {
    int i = blockIdx.x * blockDim.x + threadIdx.x;
    if (i >= TOT4) return;
    float4 eg = (i < UD4) ? __ldg(&ue[i]) : __ldg(&ie[i - UD4]);
    uint2 ua = reinterpret_cast<const uint2*>(g_bufA)[i];
    uint2 ub = reinterpret_cast<const uint2*>(g_bufB)[i];
    float2 a0 = __half22float2(u2h(ua.x));
    float2 a1 = __half22float2(u2h(ua.y));
    float2 b0 = __half22float2(u2h(ub.x));
    float2 b1 = __half22float2(u2h(ub.y));
    float4 o;
    o.x = (eg.x + a0.x + b0.x) * 0.25f;
    o.y = (eg.y + a0.y + b0.y) * 0.25f;
    o.z = (eg.z + a1.x + b1.x) * 0.25f;
    o.w = (eg.w + a1.y + b1.y) * 0.25f;
    out[i] = o;
}

extern "C" void kernel_launch(void* const* d_in, const int* in_sizes, int n_in,
                              void* d_out, int out_size) {
    const float* user_emb = (const float*)d_in[0];
    const float* item_emb = (const float*)d_in[1];
    const int*   adj_rows = (const int*)d_in[2];
    const int*   adj_cols = (const int*)d_in[3];
    const float* adj_vals = (const float*)d_in[4];
    float* out = (float*)d_out;

    __half* h0;
    __half* bufA;
    __half* bufB;
    cudaGetSymbolAddress((void**)&h0,   g_h0);
    cudaGetSymbolAddress((void**)&bufA, g_bufA);
    cudaGetSymbolAddress((void**)&bufB, g_bufB);

    const int T = 256;
    const int CONV_BLOCKS  = (TOT8 + T - 1) / T;
    const int FINAL_BLOCKS = (TOT4 + T - 1) / T;
    const int SPMM_BLOCKS  = (EE * 4 + T - 1) / T;

    // h0 = fp16(ego); bufA = bufB = 0
    conv_kernel<<<CONV_BLOCKS, T>>>((const float4*)user_emb, (const float4*)item_emb);

    // h1 = A @ h0
    spmm_kernel<<<SPMM_BLOCKS, T>>>(adj_rows, adj_cols, adj_vals, h0, bufA);
    // h2 = A @ h1
    spmm_kernel<<<SPMM_BLOCKS, T>>>(adj_rows, adj_cols, adj_vals, bufA, bufB);
    // h3 = A @ h2, accumulated onto h1 (bufA += A @ bufB)
    spmm_kernel<<<SPMM_BLOCKS, T>>>(adj_rows, adj_cols, adj_vals, bufB, bufA);

    // out = (ego + (h1+h3) + h2) / 4
    final_kernel<<<FINAL_BLOCKS, T>>>((const float4*)user_emb,
                                      (const float4*)item_emb, (float4*)out);
}

// round 5
// speedup vs baseline: 1.2831x; 1.2831x over previous
#include <cuda_runtime.h>
#include <cuda_fp16.h>
#include <cstdint>

#define NUM_USERS 100000
#define NUM_ITEMS 200000
#define NN (NUM_USERS + NUM_ITEMS)   // 300000
#define EE 2000000
#define DD 64
#define TOT (NN * DD)                // 19,200,000
#define TOT4 (TOT / 4)
#define TOT8 (TOT / 8)
#define U8  (NUM_USERS * DD / 8)
#define UD4 (NUM_USERS * DD / 4)

#define SCAN_ITEMS 1024
#define SCAN_BLOCKS ((NN + SCAN_ITEMS - 1) / SCAN_ITEMS)   // 293

// ---- allocation-free scratch -------------------------------------------------
__device__ __half g_h0[TOT];     // ego in fp16
__device__ __half g_bufA[TOT];   // h1, then h1 (+h3 via separate buffer trick not needed now)
__device__ __half g_bufB[TOT];   // h2
__device__ int    g_cnt[NN];       // histogram -> scatter offsets
__device__ int    g_rowptr[NN + 1];
__device__ int    g_bsums[512];    // block sums for scan (padded)
__device__ int2   g_edges[EE];     // (col, val bits) sorted by row

__device__ __forceinline__ uint32_t h2u(__half2 h) { return *reinterpret_cast<uint32_t*>(&h); }
__device__ __forceinline__ __half2  u2h(uint32_t u) { return *reinterpret_cast<__half2*>(&u); }

// ---------------------------------------------------------------------------
// conv: g_h0 = fp16(concat(ue, ie)).  (No zeroing needed — CSR overwrites dst.)
// ---------------------------------------------------------------------------
__global__ void __launch_bounds__(256) conv_kernel(const float4* __restrict__ ue,
                                                   const float4* __restrict__ ie) {
    int i = blockIdx.x * blockDim.x + threadIdx.x;
    if (i >= TOT8) return;
    float4 f0, f1;
    if (i < U8) {
        f0 = __ldg(&ue[2 * i]);     f1 = __ldg(&ue[2 * i + 1]);
    } else {
        f0 = __ldg(&ie[2 * (i - U8)]); f1 = __ldg(&ie[2 * (i - U8) + 1]);
    }
    uint4 h;
    h.x = h2u(__float22half2_rn(make_float2(f0.x, f0.y)));
    h.y = h2u(__float22half2_rn(make_float2(f0.z, f0.w)));
    h.z = h2u(__float22half2_rn(make_float2(f1.x, f1.y)));
    h.w = h2u(__float22half2_rn(make_float2(f1.z, f1.w)));
    reinterpret_cast<uint4*>(g_h0)[i] = h;
}

// ---------------------------------------------------------------------------
// histogram: g_cnt[r]++ per edge   (g_cnt zeroed by cudaMemsetAsync)
// ---------------------------------------------------------------------------
__global__ void __launch_bounds__(256) hist_kernel(const int* __restrict__ rows) {
    int e = blockIdx.x * blockDim.x + threadIdx.x;
    if (e >= EE) return;
    atomicAdd(&g_cnt[__ldcs(&rows[e])], 1);
}

// ---------------------------------------------------------------------------
// scan stage 1: per-block inclusive scan of g_cnt (1024 items / block of 256)
// writes inclusive values to g_rowptr[idx+1], block total to g_bsums.
// ---------------------------------------------------------------------------
__global__ void __launch_bounds__(256) scan_block_kernel() {
    __shared__ int warp_sums[8];
    int tid = threadIdx.x;
    int idx = blockIdx.x * SCAN_ITEMS + tid * 4;
    int v0 = 0, v1 = 0, v2 = 0, v3 = 0;
    if (idx + 3 < NN) {
        int4 t = *reinterpret_cast<const int4*>(&g_cnt[idx]);
        v0 = t.x; v1 = t.y; v2 = t.z; v3 = t.w;
    } else {
        if (idx     < NN) v0 = g_cnt[idx];
        if (idx + 1 < NN) v1 = g_cnt[idx + 1];
        if (idx + 2 < NN) v2 = g_cnt[idx + 2];
        if (idx + 3 < NN) v3 = g_cnt[idx + 3];
    }
    int s1 = v0 + v1, s2 = s1 + v2, s3 = s2 + v3;
    int lane = tid & 31, wid = tid >> 5;
    int x = s3;
    #pragma unroll
    for (int d = 1; d < 32; d <<= 1) {
        int y = __shfl_up_sync(0xffffffffu, x, d);
        if (lane >= d) x += y;
    }
    if (lane == 31) warp_sums[wid] = x;
    __syncthreads();
    if (wid == 0) {
        int w = (lane < 8) ? warp_sums[lane] : 0;
        #pragma unroll
        for (int d = 1; d < 8; d <<= 1) {
            int y = __shfl_up_sync(0xffffffffu, w, d);
            if (lane >= d) w += y;
        }
        if (lane < 8) warp_sums[lane] = w;
    }
    __syncthreads();
    int warp_off = (wid > 0) ? warp_sums[wid - 1] : 0;
    int te = warp_off + x - s3;                 // thread-exclusive prefix
    if (idx     < NN) g_rowptr[idx + 1] = te + v0;
    if (idx + 1 < NN) g_rowptr[idx + 2] = te + s1;
    if (idx + 2 < NN) g_rowptr[idx + 3] = te + s2;
    if (idx + 3 < NN) g_rowptr[idx + 4] = te + s3;
    if (tid == 0) {
        g_bsums[blockIdx.x] = warp_sums[7];     // block total
        if (blockIdx.x == 0) g_rowptr[0] = 0;
    }
}

// ---------------------------------------------------------------------------
// scan stage 2: one block, exclusive scan of the 293 block sums (in place)
// ---------------------------------------------------------------------------
__global__ void __launch_bounds__(512) scan_sums_kernel() {
    __shared__ int ws[16];
    int tid = threadIdx.x;
    int v = (tid < SCAN_BLOCKS) ? g_bsums[tid] : 0;
    int lane = tid & 31, wid = tid >> 5;
    int x = v;
    #pragma unroll
    for (int d = 1; d < 32; d <<= 1) {
        int y = __shfl_up_sync(0xffffffffu, x, d);
        if (lane >= d) x += y;
    }
    if (lane == 31) ws[wid] = x;
    __syncthreads();
    if (wid == 0) {
        int w = (lane < 16) ? ws[lane] : 0;
        #pragma unroll
        for (int d = 1; d < 16; d <<= 1) {
            int y = __shfl_up_sync(0xffffffffu, w, d);
            if (lane >= d) w += y;
        }
        if (lane < 16) ws[lane] = w;
    }
    __syncthreads();
    int off = (wid > 0) ? ws[wid - 1] : 0;
    if (tid < SCAN_BLOCKS) g_bsums[tid] = off + x - v;  // exclusive
}

// ---------------------------------------------------------------------------
// scan stage 3: add block offsets; also set g_cnt[r] = exclusive start offset
// (scatter cursor). rowptr[r+1] becomes final inclusive prefix.
// ---------------------------------------------------------------------------
__global__ void __launch_bounds__(256) scan_add_kernel() {
    int r = blockIdx.x * blockDim.x + threadIdx.x;
    if (r >= NN) return;
    int ex = g_bsums[r / SCAN_ITEMS];
    int inc = g_rowptr[r + 1] + ex;
    g_rowptr[r + 1] = inc;
    g_cnt[r] = inc - g_cnt[r];        // start offset for scatter
}

// ---------------------------------------------------------------------------
// scatter: place each edge (col, val) into its row bucket
// ---------------------------------------------------------------------------
__global__ void __launch_bounds__(256) scatter_kernel(const int* __restrict__ rows,
                                                      const int* __restrict__ cols,
                                                      const float* __restrict__ vals) {
    int e = blockIdx.x * blockDim.x + threadIdx.x;
    if (e >= EE) return;
    int r = __ldcs(&rows[e]);
    int c = __ldcs(&cols[e]);
    float v = __ldcs(&vals[e]);
    int pos = atomicAdd(&g_cnt[r], 1);
    g_edges[pos] = make_int2(c, __float_as_int(v));
}

// ---------------------------------------------------------------------------
// CSR SpMM (atomic-free): 8 threads/row, each owns a 16B chunk; fp32 register
// accumulation over the row's edges; single 16B fp16 store per thread.
// ---------------------------------------------------------------------------
__global__ void __launch_bounds__(256) csr_spmm_kernel(const __half* __restrict__ src,
                                                       __half* __restrict__ dst) {
    int t = blockIdx.x * blockDim.x + threadIdx.x;
    int row = t >> 3;
    if (row >= NN) return;
    int ch = (t & 7) << 3;                      // half offset 0..56 (16B chunks)
    int e   = __ldg(&g_rowptr[row]);
    int end = __ldg(&g_rowptr[row + 1]);
    float2 a0 = {0.f, 0.f}, a1 = {0.f, 0.f}, a2 = {0.f, 0.f}, a3 = {0.f, 0.f};
    #pragma unroll 2
    for (; e < end; e++) {
        int2 ev = __ldg(&g_edges[e]);
        float v = __int_as_float(ev.y);
        uint4 x = __ldg(reinterpret_cast<const uint4*>(src + (size_t)ev.x * DD + ch));
        float2 f0 = __half22float2(u2h(x.x));
        float2 f1 = __half22float2(u2h(x.y));
        float2 f2 = __half22float2(u2h(x.z));
        float2 f3 = __half22float2(u2h(x.w));
        a0.x += v * f0.x; a0.y += v * f0.y;
        a1.x += v * f1.x; a1.y += v * f1.y;
        a2.x += v * f2.x; a2.y += v * f2.y;
        a3.x += v * f3.x; a3.y += v * f3.y;
    }
    uint4 o;
    o.x = h2u(__float22half2_rn(a0));
    o.y = h2u(__float22half2_rn(a1));
    o.z = h2u(__float22half2_rn(a2));
    o.w = h2u(__float22half2_rn(a3));
    *reinterpret_cast<uint4*>(dst + (size_t)row * DD + ch) = o;
}

// ---------------------------------------------------------------------------
// final: out = (ego_fp32 + h1 + h2 + h3) * 0.25
// h3 lives in g_h0 (reused as the layer-3 destination).
// ---------------------------------------------------------------------------
__global__ void __launch_bounds__(256) final_kernel(const float4* __restrict__ ue,
                                                    const float4* __restrict__ ie,
                                                    float4* __restrict__ out) {
    int i = blockIdx.x * blockDim.x + threadIdx.x;
    if (i >= TOT4) return;
    float4 eg = (i < UD4) ? __ldg(&ue[i]) : __ldg(&ie[i - UD4]);
    uint2 ua = reinterpret_cast<const uint2*>(g_bufA)[i];
    uint2 ub = reinterpret_cast<const uint2*>(g_bufB)[i];
    uint2 uc = reinterpret_cast<const uint2*>(g_h0)[i];
    float2 a0 = __half22float2(u2h(ua.x)), a1 = __half22float2(u2h(ua.y));
    float2 b0 = __half22float2(u2h(ub.x)), b1 = __half22float2(u2h(ub.y));
    float2 c0 = __half22float2(u2h(uc.x)), c1 = __half22float2(u2h(uc.y));
    float4 o;
    o.x = (eg.x + a0.x + b0.x + c0.x) * 0.25f;
    o.y = (eg.y + a0.y + b0.y + c0.y) * 0.25f;
    o.z = (eg.z + a1.x + b1.x + c1.x) * 0.25f;
    o.w = (eg.w + a1.y + b1.y + c1.y) * 0.25f;
    out[i] = o;
}

extern "C" void kernel_launch(void* const* d_in, const int* in_sizes, int n_in,
                              void* d_out, int out_size) {
    const float* user_emb = (const float*)d_in[0];
    const float* item_emb = (const float*)d_in[1];
    const int*   adj_rows = (const int*)d_in[2];
    const int*   adj_cols = (const int*)d_in[3];
    const float* adj_vals = (const float*)d_in[4];
    float* out = (float*)d_out;

    __half *h0, *bufA, *bufB;
    int* cnt;
    cudaGetSymbolAddress((void**)&h0,   g_h0);
    cudaGetSymbolAddress((void**)&bufA, g_bufA);
    cudaGetSymbolAddress((void**)&bufB, g_bufB);
    cudaGetSymbolAddress((void**)&cnt,  g_cnt);

    const int T = 256;
    const int CONV_BLOCKS  = (TOT8 + T - 1) / T;
    const int FINAL_BLOCKS = (TOT4 + T - 1) / T;
    const int EDGE_BLOCKS  = (EE + T - 1) / T;
    const int ROW_BLOCKS   = (NN + T - 1) / T;
    const int SPMM_BLOCKS  = (NN * 8 + T - 1) / T;

    // ---- CSR build (every call; deterministic structure) ----
    cudaMemsetAsync(cnt, 0, NN * sizeof(int));
    hist_kernel<<<EDGE_BLOCKS, T>>>(adj_rows);
    scan_block_kernel<<<SCAN_BLOCKS, T>>>();
    scan_sums_kernel<<<1, 512>>>();
    scan_add_kernel<<<ROW_BLOCKS, T>>>();
    scatter_kernel<<<EDGE_BLOCKS, T>>>(adj_rows, adj_cols, adj_vals);

    // h0 = fp16(ego)
    conv_kernel<<<CONV_BLOCKS, T>>>((const float4*)user_emb, (const float4*)item_emb);

    // h1 = A @ h0 ; h2 = A @ h1 ; h3 = A @ h2 (into g_h0, no longer needed)
    csr_spmm_kernel<<<SPMM_BLOCKS, T>>>(h0,   bufA);
    csr_spmm_kernel<<<SPMM_BLOCKS, T>>>(bufA, bufB);
    csr_spmm_kernel<<<SPMM_BLOCKS, T>>>(bufB, h0);

    // out = (ego + h1 + h2 + h3) / 4
    final_kernel<<<FINAL_BLOCKS, T>>>((const float4*)user_emb,
                                      (const float4*)item_emb, (float4*)out);
}